// round 14
// baseline (speedup 1.0000x reference)
#include <cuda_runtime.h>

// Schroeder reverb: 4 series allpass + 4 parallel feedback combs, T=131072, W=128 fp32.
//
// R11: single 64MB scratch, in-place allpass via (state, payload) kernel pairs.
// R12 (this): combs 2-4 accumulate with red.global.add.f32 (write-only RED)
// instead of load+add+store -> removes 3x64MB of d_out reads AND the
// long-scoreboard dependency on the out load. One RED per address per kernel,
// kernels serialize -> deterministic, bit-identical to the RMW sum.
//
// Chain semantics (matches the jnp block-scan):
//   allpass: y[k] = -g*y[k-1] + x[k] + g*x[k-1],  y[0] = 0 (x[0] enters history)
//   comb:    y[k] =  g*y[k-1] + x[k],             y[0] = 0

#define TT 131072
#define W4 32
#define AP_P 32        // allpass payload steps per segment
#define AP_H 24        // allpass warm-up steps (0.7^24 ~ 1.9e-4 restart)
#define CB_P 32        // comb payload steps (warm-up = full prefix, exact)
#define BATCH 8
#define MAXRN 4608

__device__ float4 g_scratch[TT * W4];      // 64 MB single scratch
__device__ float4 g_stateX[MAXRN * 32];    // restart xprev
__device__ float4 g_stateY[MAXRN * 32];    // restart yprev

__device__ __forceinline__ float4 ldg_nc4(const float4* p) {
    float4 v;
    asm volatile("ld.global.nc.v4.f32 {%0,%1,%2,%3}, [%4];"
                 : "=f"(v.x), "=f"(v.y), "=f"(v.z), "=f"(v.w)
                 : "l"(p));
    return v;
}

// Ordered load: "memory" clobber pins subsequent same-address stores after it.
__device__ __forceinline__ float4 ld4_ordered(const float4* p) {
    float4 v;
    asm volatile("ld.global.v4.f32 {%0,%1,%2,%3}, [%4];"
                 : "=f"(v.x), "=f"(v.y), "=f"(v.z), "=f"(v.w)
                 : "l"(p) : "memory");
    return v;
}

__device__ __forceinline__ void red_add4(float4* p, float4 v) {
    float* f = (float*)p;
    asm volatile("red.global.add.f32 [%0], %1;" :: "l"(f + 0), "f"(v.x) : "memory");
    asm volatile("red.global.add.f32 [%0], %1;" :: "l"(f + 1), "f"(v.y) : "memory");
    asm volatile("red.global.add.f32 [%0], %1;" :: "l"(f + 2), "f"(v.z) : "memory");
    asm volatile("red.global.add.f32 [%0], %1;" :: "l"(f + 3), "f"(v.w) : "memory");
}

__device__ __forceinline__ float4 ap_step(float g, float4 xp, float4 yp, float4 xk) {
    float4 y;
    y.x = fmaf(g, xp.x - yp.x, xk.x);
    y.y = fmaf(g, xp.y - yp.y, xk.y);
    y.z = fmaf(g, xp.z - yp.z, xk.z);
    y.w = fmaf(g, xp.w - yp.w, xk.w);
    return y;
}

// ---- allpass state kernel: read-only warm-up (H steps from zero y) ----
__global__ void __launch_bounds__(128) ap_state_kernel(
    const float4* __restrict__ in, int N, int nseg, float g)
{
    const int tid = blockIdx.x * 128 + threadIdx.x;
    if (tid >= 32 * N * nseg) return;
    const int v   = tid & 31;
    const int rn  = tid >> 5;
    const int r   = rn % N;
    const int seg = rn / N;
    if (seg == 0) return;

    const int len = (TT - 1 - r) / N + 1;
    const int kbp = seg * AP_P;
    if (kbp >= len) return;
    const int kw = kbp - AP_H;                    // >= AP_P - AP_H = 8 > 0

    const int stride = N * W4;
    const int base = r * W4 + v;
    float4 xprev = ldg_nc4(in + (kw - 1) * stride + base);
    float4 yprev = make_float4(0.f, 0.f, 0.f, 0.f);

    int idx = kw * stride + base;
    int k = kw;
    while (k + BATCH <= kbp) {
        float4 xs[BATCH];
#pragma unroll
        for (int j = 0; j < BATCH; j++) xs[j] = ldg_nc4(in + idx + j * stride);
#pragma unroll
        for (int j = 0; j < BATCH; j++) {
            yprev = ap_step(g, xprev, yprev, xs[j]);
            xprev = xs[j];
        }
        idx += BATCH * stride; k += BATCH;
    }
    for (; k < kbp; ++k, idx += stride) {
        float4 xk = ldg_nc4(in + idx);
        yprev = ap_step(g, xprev, yprev, xk);
        xprev = xk;
    }
    g_stateX[rn * 32 + v] = xprev;
    g_stateY[rn * 32 + v] = yprev;
}

// ---- allpass payload kernel: may run IN-PLACE (same-thread read-before-write,
// ---- store depends on load; the one non-dependent pair uses ld4_ordered) ----
__global__ void __launch_bounds__(128) ap_payload_kernel(
    const float4* in, float4* out, int N, int nseg, float g)
{
    const int tid = blockIdx.x * 128 + threadIdx.x;
    if (tid >= 32 * N * nseg) return;
    const int v   = tid & 31;
    const int rn  = tid >> 5;
    const int r   = rn % N;
    const int seg = rn / N;

    const int len = (TT - 1 - r) / N + 1;
    const int kbp = seg * AP_P;
    if (kbp >= len) return;
    const int kend = min(len, kbp + AP_P);

    const int stride = N * W4;
    const int base = r * W4 + v;

    float4 xprev, yprev;
    int k;
    if (seg == 0) {
        xprev = ld4_ordered(in + base);               // read x[0] BEFORE
        out[base] = make_float4(0.f, 0.f, 0.f, 0.f);  // overwriting y[0]=0
        yprev = make_float4(0.f, 0.f, 0.f, 0.f);
        k = 1;
    } else {
        xprev = g_stateX[rn * 32 + v];
        yprev = g_stateY[rn * 32 + v];
        k = kbp;
    }

    int idx = k * stride + base;
    while (k + BATCH <= kend) {
        float4 xs[BATCH];
#pragma unroll
        for (int j = 0; j < BATCH; j++) xs[j] = ldg_nc4(in + idx + j * stride);
#pragma unroll
        for (int j = 0; j < BATCH; j++) {
            float4 y = ap_step(g, xprev, yprev, xs[j]);
            out[idx + j * stride] = y;
            xprev = xs[j];
            yprev = y;
        }
        idx += BATCH * stride; k += BATCH;
    }
    for (; k < kend; ++k, idx += stride) {
        float4 xk = ldg_nc4(in + idx);
        float4 y = ap_step(g, xprev, yprev, xk);
        out[idx] = y;
        xprev = xk;
        yprev = y;
    }
}

// ---- segmented feedback comb, EXACT full-prefix warm-up (chain len <= 118).
// MODE 0: plain store (first comb; also clears 0xAA poison).
// MODE 1: write-only RED accumulate (one RED per address per kernel;
//         kernels serialize -> deterministic, same fp32 sum as RMW).
template <int MODE>
__global__ void __launch_bounds__(128) comb_kernel(
    const float4* __restrict__ in, float4* out, int N, int nseg, float g)
{
    const int tid = blockIdx.x * 128 + threadIdx.x;
    if (tid >= 32 * N * nseg) return;
    const int v   = tid & 31;
    const int rn  = tid >> 5;
    const int r   = rn % N;
    const int seg = rn / N;

    const int len = (TT - 1 - r) / N + 1;
    const int kbp = seg * CB_P;
    if (kbp >= len) return;
    const int kend = min(len, kbp + CB_P);

    const int stride = N * W4;
    float4 yprev = make_float4(0.f, 0.f, 0.f, 0.f);
    int k = 1;                                    // exact: replay from head
    if (seg == 0 && MODE == 0)
        out[r * W4 + v] = make_float4(0.f, 0.f, 0.f, 0.f);   // y[0] = 0

    int idx = stride + r * W4 + v;
    const int kp = (kbp > 1) ? kbp : 1;

    while (k + BATCH <= kp) {
        float4 xs[BATCH];
#pragma unroll
        for (int j = 0; j < BATCH; j++) xs[j] = ldg_nc4(in + idx + j * stride);
#pragma unroll
        for (int j = 0; j < BATCH; j++) {
            yprev.x = fmaf(g, yprev.x, xs[j].x);
            yprev.y = fmaf(g, yprev.y, xs[j].y);
            yprev.z = fmaf(g, yprev.z, xs[j].z);
            yprev.w = fmaf(g, yprev.w, xs[j].w);
        }
        idx += BATCH * stride; k += BATCH;
    }
    for (; k < kp; ++k, idx += stride) {
        float4 xk = ldg_nc4(in + idx);
        yprev.x = fmaf(g, yprev.x, xk.x);
        yprev.y = fmaf(g, yprev.y, xk.y);
        yprev.z = fmaf(g, yprev.z, xk.z);
        yprev.w = fmaf(g, yprev.w, xk.w);
    }

    while (k + BATCH <= kend) {
        float4 xs[BATCH];
#pragma unroll
        for (int j = 0; j < BATCH; j++) xs[j] = ldg_nc4(in + idx + j * stride);
#pragma unroll
        for (int j = 0; j < BATCH; j++) {
            float4 y;
            y.x = fmaf(g, yprev.x, xs[j].x);
            y.y = fmaf(g, yprev.y, xs[j].y);
            y.z = fmaf(g, yprev.z, xs[j].z);
            y.w = fmaf(g, yprev.w, xs[j].w);
            if (MODE == 0) out[idx + j * stride] = y;
            else           red_add4(out + idx + j * stride, y);
            yprev = y;
        }
        idx += BATCH * stride; k += BATCH;
    }
    for (; k < kend; ++k, idx += stride) {
        float4 xk = ldg_nc4(in + idx);
        float4 y;
        y.x = fmaf(g, yprev.x, xk.x);
        y.y = fmaf(g, yprev.y, xk.y);
        y.z = fmaf(g, yprev.z, xk.z);
        y.w = fmaf(g, yprev.w, xk.w);
        if (MODE == 0) out[idx] = y;
        else           red_add4(out + idx, y);
        yprev = y;
    }
}

static inline int grid_of(int N, int nseg) { return (32 * N * nseg + 127) / 128; }
static inline int nseg_ap(int N) { int L = (TT - 1) / N + 1; return (L + AP_P - 1) / AP_P; }
static inline int nseg_cb(int N) { int L = (TT - 1) / N + 1; return (L + CB_P - 1) / CB_P; }

extern "C" void kernel_launch(void* const* d_in, const int* in_sizes, int n_in,
                              void* d_out, int out_size)
{
    const float4* x = (const float4*)d_in[0];
    float4* out = (float4*)d_out;

    float4* S;
    cudaGetSymbolAddress((void**)&S, g_scratch);

    // Series allpass chain. Stage 1: x -> S. Stages 2-4: in-place on S
    // (state kernel reads warm-up regions BEFORE payload overwrites them).
    { int N = 225, s = nseg_ap(N);
      ap_state_kernel  <<<grid_of(N, s), 128>>>(x, N, s, 0.7f);
      ap_payload_kernel<<<grid_of(N, s), 128>>>(x, S, N, s, 0.7f); }
    { int N = 556, s = nseg_ap(N);
      ap_state_kernel  <<<grid_of(N, s), 128>>>(S, N, s, 0.7f);
      ap_payload_kernel<<<grid_of(N, s), 128>>>(S, S, N, s, 0.7f); }
    { int N = 441, s = nseg_ap(N);
      ap_state_kernel  <<<grid_of(N, s), 128>>>(S, N, s, 0.7f);
      ap_payload_kernel<<<grid_of(N, s), 128>>>(S, S, N, s, 0.7f); }
    { int N = 341, s = nseg_ap(N);
      ap_state_kernel  <<<grid_of(N, s), 128>>>(S, N, s, 0.7f);
      ap_payload_kernel<<<grid_of(N, s), 128>>>(S, S, N, s, 0.7f); }

    // Parallel comb bank summed into d_out. Comb 1: plain store (covers every
    // element once, clears poison). Combs 2-4: write-only RED accumulate.
    { int N = 1116, s = nseg_cb(N); comb_kernel<0><<<grid_of(N, s), 128>>>(S, out, N, s, 0.84f); }
    { int N = 1188, s = nseg_cb(N); comb_kernel<1><<<grid_of(N, s), 128>>>(S, out, N, s, 0.82f); }
    { int N = 1277, s = nseg_cb(N); comb_kernel<1><<<grid_of(N, s), 128>>>(S, out, N, s, 0.80f); }
    { int N = 1356, s = nseg_cb(N); comb_kernel<1><<<grid_of(N, s), 128>>>(S, out, N, s, 0.78f); }
}

// round 17
// speedup vs baseline: 1.2778x; 1.2778x over previous
#include <cuda_runtime.h>
#include <cstdint>

// Schroeder reverb: 4 series allpass + 4 parallel feedback combs, T=131072, W=128 fp32.
//
// R14 post-mortem: scalar red.global.add regressed +57us (4 scalar LSU/LTS ops
// per float4 vs one 128-bit RMW). Reverted to R11's float4 RMW combs.
// R15 addition: L2 eviction hints (createpolicy + L2::cache_hint):
//   - d_out and stage-1 x reads -> evict_first (single-touch traffic; don't
//     let it displace the 64MB scratch S from the 126MB L2)
//   - S reads/writes -> evict_last
//
// Chain semantics (matches the jnp block-scan):
//   allpass: y[k] = -g*y[k-1] + x[k] + g*x[k-1],  y[0] = 0 (x[0] enters history)
//   comb:    y[k] =  g*y[k-1] + x[k],             y[0] = 0

#define TT 131072
#define W4 32
#define AP_P 32        // allpass payload steps per segment
#define AP_H 24        // allpass warm-up steps (0.7^24 ~ 1.9e-4 restart)
#define CB_P 32        // comb payload steps (warm-up = full prefix, exact)
#define BATCH 8
#define MAXRN 4608

__device__ float4 g_scratch[TT * W4];      // 64 MB single scratch
__device__ float4 g_stateX[MAXRN * 32];
__device__ float4 g_stateY[MAXRN * 32];

__device__ __forceinline__ uint64_t pol_first() {
    uint64_t p;
    asm("createpolicy.fractional.L2::evict_first.b64 %0, 1.0;" : "=l"(p));
    return p;
}
__device__ __forceinline__ uint64_t pol_last() {
    uint64_t p;
    asm("createpolicy.fractional.L2::evict_last.b64 %0, 1.0;" : "=l"(p));
    return p;
}

// read-only-in-kernel load (texture path) with L2 hint
__device__ __forceinline__ float4 ldg_nc4_h(const float4* p, uint64_t pol) {
    float4 v;
    asm volatile("ld.global.nc.L2::cache_hint.v4.f32 {%0,%1,%2,%3}, [%4], %5;"
                 : "=f"(v.x), "=f"(v.y), "=f"(v.z), "=f"(v.w)
                 : "l"(p), "l"(pol));
    return v;
}
// generic load with L2 hint (for d_out RMW: NOT .nc, kernel also writes it)
__device__ __forceinline__ float4 ld4_h(const float4* p, uint64_t pol) {
    float4 v;
    asm volatile("ld.global.L2::cache_hint.v4.f32 {%0,%1,%2,%3}, [%4], %5;"
                 : "=f"(v.x), "=f"(v.y), "=f"(v.z), "=f"(v.w)
                 : "l"(p), "l"(pol));
    return v;
}
__device__ __forceinline__ void st4_h(float4* p, float4 v, uint64_t pol) {
    asm volatile("st.global.L2::cache_hint.v4.f32 [%0], {%1,%2,%3,%4}, %5;"
                 :: "l"(p), "f"(v.x), "f"(v.y), "f"(v.z), "f"(v.w), "l"(pol)
                 : "memory");
}
// Ordered load: "memory" clobber pins the subsequent same-address store after it.
__device__ __forceinline__ float4 ld4_ordered(const float4* p) {
    float4 v;
    asm volatile("ld.global.v4.f32 {%0,%1,%2,%3}, [%4];"
                 : "=f"(v.x), "=f"(v.y), "=f"(v.z), "=f"(v.w)
                 : "l"(p) : "memory");
    return v;
}

__device__ __forceinline__ float4 ap_step(float g, float4 xp, float4 yp, float4 xk) {
    float4 y;
    y.x = fmaf(g, xp.x - yp.x, xk.x);
    y.y = fmaf(g, xp.y - yp.y, xk.y);
    y.z = fmaf(g, xp.z - yp.z, xk.z);
    y.w = fmaf(g, xp.w - yp.w, xk.w);
    return y;
}

// ---- allpass state kernel: read-only warm-up (H steps from zero y).
// IN_LAST=false for stage 1 (reads dead-after-stage x -> evict_first).
template <bool IN_LAST>
__global__ void __launch_bounds__(128) ap_state_kernel(
    const float4* __restrict__ in, int N, int nseg, float g)
{
    const uint64_t pin = IN_LAST ? pol_last() : pol_first();
    const int tid = blockIdx.x * 128 + threadIdx.x;
    if (tid >= 32 * N * nseg) return;
    const int v   = tid & 31;
    const int rn  = tid >> 5;
    const int r   = rn % N;
    const int seg = rn / N;
    if (seg == 0) return;

    const int len = (TT - 1 - r) / N + 1;
    const int kbp = seg * AP_P;
    if (kbp >= len) return;
    const int kw = kbp - AP_H;                    // >= AP_P - AP_H = 8 > 0

    const int stride = N * W4;
    const int base = r * W4 + v;
    float4 xprev = ldg_nc4_h(in + (kw - 1) * stride + base, pin);
    float4 yprev = make_float4(0.f, 0.f, 0.f, 0.f);

    int idx = kw * stride + base;
    int k = kw;
    while (k + BATCH <= kbp) {
        float4 xs[BATCH];
#pragma unroll
        for (int j = 0; j < BATCH; j++) xs[j] = ldg_nc4_h(in + idx + j * stride, pin);
#pragma unroll
        for (int j = 0; j < BATCH; j++) {
            yprev = ap_step(g, xprev, yprev, xs[j]);
            xprev = xs[j];
        }
        idx += BATCH * stride; k += BATCH;
    }
    for (; k < kbp; ++k, idx += stride) {
        float4 xk = ldg_nc4_h(in + idx, pin);
        yprev = ap_step(g, xprev, yprev, xk);
        xprev = xk;
    }
    g_stateX[rn * 32 + v] = xprev;
    g_stateY[rn * 32 + v] = yprev;
}

// ---- allpass payload kernel: may run IN-PLACE (same-thread read-before-write;
// store value depends on the load; the one non-dependent pair uses ld4_ordered).
template <bool IN_LAST>
__global__ void __launch_bounds__(128) ap_payload_kernel(
    const float4* in, float4* out, int N, int nseg, float g)
{
    const uint64_t pin  = IN_LAST ? pol_last() : pol_first();
    const uint64_t pout = pol_last();             // S writes stay L2-resident
    const int tid = blockIdx.x * 128 + threadIdx.x;
    if (tid >= 32 * N * nseg) return;
    const int v   = tid & 31;
    const int rn  = tid >> 5;
    const int r   = rn % N;
    const int seg = rn / N;

    const int len = (TT - 1 - r) / N + 1;
    const int kbp = seg * AP_P;
    if (kbp >= len) return;
    const int kend = min(len, kbp + AP_P);

    const int stride = N * W4;
    const int base = r * W4 + v;

    float4 xprev, yprev;
    int k;
    if (seg == 0) {
        xprev = ld4_ordered(in + base);               // read x[0] BEFORE
        out[base] = make_float4(0.f, 0.f, 0.f, 0.f);  // overwriting y[0]=0
        yprev = make_float4(0.f, 0.f, 0.f, 0.f);
        k = 1;
    } else {
        xprev = g_stateX[rn * 32 + v];
        yprev = g_stateY[rn * 32 + v];
        k = kbp;
    }

    int idx = k * stride + base;
    while (k + BATCH <= kend) {
        float4 xs[BATCH];
#pragma unroll
        for (int j = 0; j < BATCH; j++) xs[j] = ldg_nc4_h(in + idx + j * stride, pin);
#pragma unroll
        for (int j = 0; j < BATCH; j++) {
            float4 y = ap_step(g, xprev, yprev, xs[j]);
            st4_h(out + idx + j * stride, y, pout);   // depends on xs[j]
            xprev = xs[j];
            yprev = y;
        }
        idx += BATCH * stride; k += BATCH;
    }
    for (; k < kend; ++k, idx += stride) {
        float4 xk = ldg_nc4_h(in + idx, pin);
        float4 y = ap_step(g, xprev, yprev, xk);
        st4_h(out + idx, y, pout);
        xprev = xk;
        yprev = y;
    }
}

// ---- segmented feedback comb, EXACT full-prefix warm-up (chain len <= 118).
// MODE 0: plain store (first comb; clears 0xAA poison).
// MODE 1: float4 RMW accumulate (one touch per address per kernel; kernels
//         serialize -> deterministic). All d_out traffic hinted evict_first.
template <int MODE>
__global__ void __launch_bounds__(128) comb_kernel(
    const float4* __restrict__ in, float4* out, int N, int nseg, float g)
{
    const uint64_t pin  = pol_last();    // S: keep resident
    const uint64_t pout = pol_first();   // out: single-touch, don't pollute L2
    const int tid = blockIdx.x * 128 + threadIdx.x;
    if (tid >= 32 * N * nseg) return;
    const int v   = tid & 31;
    const int rn  = tid >> 5;
    const int r   = rn % N;
    const int seg = rn / N;

    const int len = (TT - 1 - r) / N + 1;
    const int kbp = seg * CB_P;
    if (kbp >= len) return;
    const int kend = min(len, kbp + CB_P);

    const int stride = N * W4;
    float4 yprev = make_float4(0.f, 0.f, 0.f, 0.f);
    int k = 1;                                    // exact: replay from head
    if (seg == 0 && MODE == 0)
        st4_h(out + r * W4 + v, make_float4(0.f, 0.f, 0.f, 0.f), pout);  // y[0]=0

    int idx = stride + r * W4 + v;
    const int kp = (kbp > 1) ? kbp : 1;

    while (k + BATCH <= kp) {
        float4 xs[BATCH];
#pragma unroll
        for (int j = 0; j < BATCH; j++) xs[j] = ldg_nc4_h(in + idx + j * stride, pin);
#pragma unroll
        for (int j = 0; j < BATCH; j++) {
            yprev.x = fmaf(g, yprev.x, xs[j].x);
            yprev.y = fmaf(g, yprev.y, xs[j].y);
            yprev.z = fmaf(g, yprev.z, xs[j].z);
            yprev.w = fmaf(g, yprev.w, xs[j].w);
        }
        idx += BATCH * stride; k += BATCH;
    }
    for (; k < kp; ++k, idx += stride) {
        float4 xk = ldg_nc4_h(in + idx, pin);
        yprev.x = fmaf(g, yprev.x, xk.x);
        yprev.y = fmaf(g, yprev.y, xk.y);
        yprev.z = fmaf(g, yprev.z, xk.z);
        yprev.w = fmaf(g, yprev.w, xk.w);
    }

    while (k + BATCH <= kend) {
        float4 xs[BATCH];
#pragma unroll
        for (int j = 0; j < BATCH; j++) xs[j] = ldg_nc4_h(in + idx + j * stride, pin);
        float4 os[BATCH];
        if (MODE == 1) {
#pragma unroll
            for (int j = 0; j < BATCH; j++) os[j] = ld4_h(out + idx + j * stride, pout);
        }
#pragma unroll
        for (int j = 0; j < BATCH; j++) {
            float4 y;
            y.x = fmaf(g, yprev.x, xs[j].x);
            y.y = fmaf(g, yprev.y, xs[j].y);
            y.z = fmaf(g, yprev.z, xs[j].z);
            y.w = fmaf(g, yprev.w, xs[j].w);
            if (MODE == 0) {
                st4_h(out + idx + j * stride, y, pout);
            } else {
                float4 o = os[j];
                o.x += y.x; o.y += y.y; o.z += y.z; o.w += y.w;
                st4_h(out + idx + j * stride, o, pout);
            }
            yprev = y;
        }
        idx += BATCH * stride; k += BATCH;
    }
    for (; k < kend; ++k, idx += stride) {
        float4 xk = ldg_nc4_h(in + idx, pin);
        float4 y;
        y.x = fmaf(g, yprev.x, xk.x);
        y.y = fmaf(g, yprev.y, xk.y);
        y.z = fmaf(g, yprev.z, xk.z);
        y.w = fmaf(g, yprev.w, xk.w);
        if (MODE == 0) {
            st4_h(out + idx, y, pout);
        } else {
            float4 o = ld4_h(out + idx, pout);
            o.x += y.x; o.y += y.y; o.z += y.z; o.w += y.w;
            st4_h(out + idx, o, pout);
        }
        yprev = y;
    }
}

static inline int grid_of(int N, int nseg) { return (32 * N * nseg + 127) / 128; }
static inline int nseg_ap(int N) { int L = (TT - 1) / N + 1; return (L + AP_P - 1) / AP_P; }
static inline int nseg_cb(int N) { int L = (TT - 1) / N + 1; return (L + CB_P - 1) / CB_P; }

extern "C" void kernel_launch(void* const* d_in, const int* in_sizes, int n_in,
                              void* d_out, int out_size)
{
    const float4* x = (const float4*)d_in[0];
    float4* out = (float4*)d_out;

    float4* S;
    cudaGetSymbolAddress((void**)&S, g_scratch);

    // Series allpass chain. Stage 1: x -> S (x hinted evict_first; dead after).
    // Stages 2-4: in-place on S (state kernel reads warm-up regions BEFORE the
    // payload overwrites them; launches serialize on the stream).
    { int N = 225, s = nseg_ap(N);
      ap_state_kernel<false>  <<<grid_of(N, s), 128>>>(x, N, s, 0.7f);
      ap_payload_kernel<false><<<grid_of(N, s), 128>>>(x, S, N, s, 0.7f); }
    { int N = 556, s = nseg_ap(N);
      ap_state_kernel<true>   <<<grid_of(N, s), 128>>>(S, N, s, 0.7f);
      ap_payload_kernel<true> <<<grid_of(N, s), 128>>>(S, S, N, s, 0.7f); }
    { int N = 441, s = nseg_ap(N);
      ap_state_kernel<true>   <<<grid_of(N, s), 128>>>(S, N, s, 0.7f);
      ap_payload_kernel<true> <<<grid_of(N, s), 128>>>(S, S, N, s, 0.7f); }
    { int N = 341, s = nseg_ap(N);
      ap_state_kernel<true>   <<<grid_of(N, s), 128>>>(S, N, s, 0.7f);
      ap_payload_kernel<true> <<<grid_of(N, s), 128>>>(S, S, N, s, 0.7f); }

    // Parallel comb bank summed into d_out. Comb 1: plain store. Combs 2-4:
    // float4 RMW accumulate (R11 mechanism; R14 proved scalar RED is worse).
    { int N = 1116, s = nseg_cb(N); comb_kernel<0><<<grid_of(N, s), 128>>>(S, out, N, s, 0.84f); }
    { int N = 1188, s = nseg_cb(N); comb_kernel<1><<<grid_of(N, s), 128>>>(S, out, N, s, 0.82f); }
    { int N = 1277, s = nseg_cb(N); comb_kernel<1><<<grid_of(N, s), 128>>>(S, out, N, s, 0.80f); }
    { int N = 1356, s = nseg_cb(N); comb_kernel<1><<<grid_of(N, s), 128>>>(S, out, N, s, 0.78f); }
}